// round 2
// baseline (speedup 1.0000x reference)
#include <cuda_runtime.h>

#define B_CHAIN 16384
#define S_SIDE 15
#define NATM (1 + B_CHAIN + B_CHAIN * S_SIDE)

#define K1_BLOCKS 128
#define K1_THREADS 128   // items per block; K1_BLOCKS*K1_THREADS == B_CHAIN

// Scratch (device globals: no allocation allowed in kernel_launch)
__device__ float g_local[12 * B_CHAIN];    // block-local inclusive scans (SoA)
__device__ float g_agg[12 * K1_BLOCKS];    // block aggregates (SoA)
__device__ float g_pre[12 * K1_BLOCKS];    // exclusive block prefixes (SoA)

struct Aff { float m[12]; };  // row-major 3x4 affine; m[r*4+3] = translation

__device__ __forceinline__ Aff aff_identity() {
    Aff I;
#pragma unroll
    for (int k = 0; k < 12; ++k) I.m[k] = 0.0f;
    I.m[0] = I.m[5] = I.m[10] = 1.0f;
    return I;
}

// C = A * B (affine compose, bottom row implicit [0 0 0 1])
__device__ __forceinline__ Aff aff_mul(const Aff& A, const Aff& B) {
    Aff C;
#pragma unroll
    for (int r = 0; r < 3; ++r) {
#pragma unroll
        for (int c = 0; c < 4; ++c) {
            float s = A.m[r*4+0] * B.m[0*4+c]
                    + A.m[r*4+1] * B.m[1*4+c]
                    + A.m[r*4+2] * B.m[2*4+c];
            if (c == 3) s += A.m[r*4+3];
            C.m[r*4+c] = s;
        }
    }
    return C;
}

// Build the per-node homogeneous transform.
// doftype==2 (bond): Rx(d0) Rz(d1) T(d2,0,0) Rx(d3)  -- closed form
// doftype==1 (jump): T(d0,d1,d2) Rz(d5) Ry(d4) Rx(d3) -- closed form (ZYX Euler)
// doftype==0: identity
__device__ __forceinline__ Aff build_ht(int n,
                                        const float4* __restrict__ dofs4,
                                        const float* __restrict__ full_dofs,
                                        const int* __restrict__ doftype) {
    int dt = doftype[n];
    if (dt == 0) return aff_identity();

    float4 d = dofs4[n - 1];   // full[n][0..3] = dofs[(n-1)*4 + 0..3]
    Aff H;
    if (dt == 2) {
        float sa, ca, sb, cb, sc, cc;
        sincosf(d.x, &sa, &ca);
        sincosf(d.y, &sb, &cb);
        sincosf(d.w, &sc, &cc);
        float x = d.z;
        H.m[0] = cb;      H.m[1]  = -sb * cc;            H.m[2]  = sb * sc;             H.m[3]  = cb * x;
        H.m[4] = ca * sb; H.m[5]  = ca * cb * cc - sa*sc; H.m[6]  = -ca * cb * sc - sa*cc; H.m[7]  = ca * sb * x;
        H.m[8] = sa * sb; H.m[9]  = sa * cb * cc + ca*sc; H.m[10] = -sa * cb * sc + ca*cc; H.m[11] = sa * sb * x;
    } else {
        // jump: d4, d5 come from full_dofs input (zeros in this dataset, but be general)
        float a = d.w;
        float b = full_dofs[n * 9 + 4];
        float g = full_dofs[n * 9 + 5];
        float sa, ca, sb, cb, sg, cg;
        sincosf(a, &sa, &ca);
        sincosf(b, &sb, &cb);
        sincosf(g, &sg, &cg);
        H.m[0] = cg * cb; H.m[1]  = cg * sb * sa - sg * ca; H.m[2]  = cg * sb * ca + sg * sa; H.m[3]  = d.x;
        H.m[4] = sg * cb; H.m[5]  = sg * sb * sa + cg * ca; H.m[6]  = sg * sb * ca - cg * sa; H.m[7]  = d.y;
        H.m[8] = -sb;     H.m[9]  = cb * sa;                H.m[10] = cb * ca;                H.m[11] = d.z;
    }
    return H;
}

// ---------------- K1: per-node transform + block-local inclusive scan --------
__global__ void __launch_bounds__(K1_THREADS)
k1_local_scan(const float4* __restrict__ dofs4,
              const float* __restrict__ full_dofs,
              const int* __restrict__ doftype) {
    __shared__ float sm[2][K1_THREADS][13];  // pad 12->13: conflict-free
    int t = threadIdx.x;
    int item = blockIdx.x * K1_THREADS + t;  // 0..B_CHAIN-1
    int n = item + 1;                        // backbone node id (node 0 = identity)

    Aff M = build_ht(n, dofs4, full_dofs, doftype);

    int cur = 0;
#pragma unroll
    for (int k = 0; k < 12; ++k) sm[0][t][k] = M.m[k];
    __syncthreads();

    for (int off = 1; off < K1_THREADS; off <<= 1) {
        if (t >= off) {
            Aff P;
#pragma unroll
            for (int k = 0; k < 12; ++k) P.m[k] = sm[cur][t - off][k];
            M = aff_mul(P, M);
        }
        cur ^= 1;
#pragma unroll
        for (int k = 0; k < 12; ++k) sm[cur][t][k] = M.m[k];
        __syncthreads();
    }

    // inclusive scan within block -> global scratch (SoA, coalesced)
#pragma unroll
    for (int k = 0; k < 12; ++k) g_local[k * B_CHAIN + item] = M.m[k];

    if (t == K1_THREADS - 1) {
#pragma unroll
        for (int k = 0; k < 12; ++k) g_agg[k * K1_BLOCKS + blockIdx.x] = M.m[k];
    }
}

// ---------------- K2: scan the block aggregates -> exclusive prefixes --------
__global__ void __launch_bounds__(K1_BLOCKS)
k2_block_scan() {
    __shared__ float sm[2][K1_BLOCKS][13];
    int t = threadIdx.x;
    Aff M;
#pragma unroll
    for (int k = 0; k < 12; ++k) M.m[k] = g_agg[k * K1_BLOCKS + t];

    int cur = 0;
#pragma unroll
    for (int k = 0; k < 12; ++k) sm[0][t][k] = M.m[k];
    __syncthreads();

    for (int off = 1; off < K1_BLOCKS; off <<= 1) {
        if (t >= off) {
            Aff P;
#pragma unroll
            for (int k = 0; k < 12; ++k) P.m[k] = sm[cur][t - off][k];
            M = aff_mul(P, M);
        }
        cur ^= 1;
#pragma unroll
        for (int k = 0; k < 12; ++k) sm[cur][t][k] = M.m[k];
        __syncthreads();
    }

    // exclusive prefix: pre[t] = inclusive[t-1], pre[0] = I
    Aff P;
    if (t == 0) {
        P = aff_identity();
    } else {
#pragma unroll
        for (int k = 0; k < 12; ++k) P.m[k] = sm[cur][t - 1][k];
    }
#pragma unroll
    for (int k = 0; k < 12; ++k) g_pre[k * K1_BLOCKS + t] = P.m[k];
}

// ---------------- K3: finalize backbone + walk side chains -------------------
__global__ void __launch_bounds__(K1_THREADS)
k3_finalize(const float4* __restrict__ dofs4,
            const float* __restrict__ full_dofs,
            const int* __restrict__ doftype,
            const int* __restrict__ kin_id,
            float* __restrict__ out) {
    int t = threadIdx.x;
    int item = blockIdx.x * K1_THREADS + t;
    int n = item + 1;  // backbone node id

    Aff pre;
#pragma unroll
    for (int k = 0; k < 12; ++k) pre.m[k] = g_pre[k * K1_BLOCKS + blockIdx.x];

    Aff L;
#pragma unroll
    for (int k = 0; k < 12; ++k) L.m[k] = g_local[k * B_CHAIN + item];

    Aff M = aff_mul(pre, L);  // global transform of backbone node n

    {
        int o = kin_id[n];
        out[o * 3 + 0] = M.m[3];
        out[o * 3 + 1] = M.m[7];
        out[o * 3 + 2] = M.m[11];
    }

    // side chain hanging off backbone node n: nodes nb .. nb+14
    int nb = 1 + B_CHAIN + item * S_SIDE;
#pragma unroll 3
    for (int d = 0; d < S_SIDE; ++d) {
        int ns = nb + d;
        Aff H = build_ht(ns, dofs4, full_dofs, doftype);
        M = aff_mul(M, H);
        int o = kin_id[ns];
        out[o * 3 + 0] = M.m[3];
        out[o * 3 + 1] = M.m[7];
        out[o * 3 + 2] = M.m[11];
    }
}

// ---------------- launch -----------------------------------------------------
extern "C" void kernel_launch(void* const* d_in, const int* in_sizes, int n_in,
                              void* d_out, int out_size) {
    // metadata order: dofs, full_dofs, node_idx, dof_idx, doftype,
    //                 gen0_nodes, gen1_nodes, gen1_parents, kin_id
    const float4* dofs4     = (const float4*)d_in[0];
    const float*  full_dofs = (const float*)d_in[1];
    const int*    doftype   = (const int*)d_in[4];
    const int*    kin_id    = (const int*)d_in[8];
    float* out = (float*)d_out;

    k1_local_scan<<<K1_BLOCKS, K1_THREADS>>>(dofs4, full_dofs, doftype);
    k2_block_scan<<<1, K1_BLOCKS>>>();
    k3_finalize<<<K1_BLOCKS, K1_THREADS>>>(dofs4, full_dofs, doftype, kin_id, out);
}